// round 7
// baseline (speedup 1.0000x reference)
#include <cuda_runtime.h>
#include <cstdint>

#define TLEN 4096
#define NH 32
#define HS 64
#define DIM (NH*HS)
#define DEPTH 8
#define STRIDE 336   // floats/slot: w64|k64|a64|b64|r64|v8|pad

// grid=128 (32 heads x 4 quarters), block=64 = 2 warps; warp = 4 groups x 8
// lanes, lane owns TWO rows' j-slices (f32x2-packed). cp.async ring DEPTH=8,
// 8x-unrolled loop with compile-time slots.
//
// sa-lookahead decomposition (takes shfl chain off the per-step recurrence):
//   sa_{t+1} = A_t + sa_t*B_t + v_t*C_t
//   A = dot(S_t .* w_t, a_{t+1}),  B = dot(b_t, a_{t+1}),  C = dot(k_t, a_{t+1})
// The step-t state update uses sa_t (known at step entry). a_{t+2} is
// register-prefetched (wait_group 5) so dot inputs have a step of slack.
// y_t reduction deferred one iteration.

__device__ __forceinline__ uint32_t smem_u32(const void* p) {
    return (uint32_t)__cvta_generic_to_shared(p);
}

typedef unsigned long long u64;

#define MUL2(d,a,b)   asm("mul.rn.f32x2 %0, %1, %2;"     : "=l"(d) : "l"(a), "l"(b))
#define FMA2(d,a,b,c) asm("fma.rn.f32x2 %0, %1, %2, %3;" : "=l"(d) : "l"(a), "l"(b), "l"(c))
#define PACK2(d,lo,hi)   asm("mov.b64 %0, {%1, %2};" : "=l"(d) : "f"(lo), "f"(hi))
#define UNPACK2(lo,hi,v) asm("mov.b64 {%0, %1}, %2;" : "=f"(lo), "=f"(hi) : "l"(v))

#define DOT8(res, X, Y) do { \
    u64 _p; MUL2(_p, X[0], Y[0]); FMA2(_p, X[1], Y[1], _p); \
    FMA2(_p, X[2], Y[2], _p);     FMA2(_p, X[3], Y[3], _p); \
    float _lo, _hi; UNPACK2(_lo, _hi, _p); res = _lo + _hi; } while(0)

#define RED8(x) do { \
    x += __shfl_xor_sync(0xffffffffu, x, 1); \
    x += __shfl_xor_sync(0xffffffffu, x, 2); \
    x += __shfl_xor_sync(0xffffffffu, x, 4); } while(0)

#define LD4x2(dst, ptr) do { \
    const ulonglong2* _p = (const ulonglong2*)(ptr); \
    ulonglong2 _x0 = _p[0], _x1 = _p[1]; \
    dst[0]=_x0.x; dst[1]=_x0.y; dst[2]=_x1.x; dst[3]=_x1.y; } while(0)

__global__ void __launch_bounds__(64, 1) wkv7_kernel(
    const float* __restrict__ rr, const float* __restrict__ ww,
    const float* __restrict__ kk, const float* __restrict__ vv_,
    const float* __restrict__ aa, const float* __restrict__ bb,
    const float* __restrict__ s0, float* __restrict__ y, float* __restrict__ sout)
{
    const int blk   = blockIdx.x;
    const int h     = blk >> 2;
    const int q     = blk & 3;
    const int tid   = threadIdx.x;
    const int warp  = tid >> 5;
    const int lane  = tid & 31;
    const int lane8 = lane & 7;
    const int g     = lane >> 3;
    const int j0    = lane8 * 8;
    const int hbase = h * HS;
    const int r0    = q * 16 + warp * 8 + g * 2;

    __shared__ __align__(16) float ring[2][DEPTH][STRIDE];

    u64 sA[4], sB[4];
    {
        const float* sp = s0 + ((size_t)h * HS + r0) * HS + j0;
        LD4x2(sA, sp);
        LD4x2(sB, sp + HS);
    }

    // cp.async lane routing
    const float *g1, *g2, *g3 = 0;
    uint32_t o1, o2, o3 = 0;
    if (lane < 16) { g1 = ww + hbase + lane * 4;        o1 = 0   + lane * 4; }
    else           { g1 = kk + hbase + (lane - 16) * 4; o1 = 64  + (lane - 16) * 4; }
    if (lane < 16) { g2 = aa + hbase + lane * 4;        o2 = 128 + lane * 4; }
    else           { g2 = bb + hbase + (lane - 16) * 4; o2 = 192 + (lane - 16) * 4; }
    if (lane < 16)      { g3 = rr + hbase + lane * 4;                      o3 = 256 + lane * 4; }
    else if (lane < 18) { g3 = vv_ + hbase + q * 16 + warp * 8 + (lane - 16) * 4; o3 = 320 + (lane - 16) * 4; }

#define ISSUE(tt, ss) do { \
    size_t _off = (size_t)(tt) * DIM; \
    uint32_t _sb = smem_u32(&ring[warp][ss][0]); \
    asm volatile("cp.async.cg.shared.global [%0], [%1], 16;" :: "r"(_sb + o1*4u), "l"(g1 + _off)); \
    asm volatile("cp.async.cg.shared.global [%0], [%1], 16;" :: "r"(_sb + o2*4u), "l"(g2 + _off)); \
    if (g3) asm volatile("cp.async.cg.shared.global [%0], [%1], 16;" :: "r"(_sb + o3*4u), "l"(g3 + _off)); \
    asm volatile("cp.async.commit_group;"); \
} while(0)

    #pragma unroll
    for (int i = 0; i < DEPTH; i++) ISSUE(i, i);

    // sa_0 = dot(S_0, a_0); a2 = a_1  (direct LDG, latency amortized once)
    float sa0, sa1;
    u64 a2[4];
    {
        u64 a0r[4];
        LD4x2(a0r, aa + hbase + j0);
        DOT8(sa0, sA, a0r);
        DOT8(sa1, sB, a0r);
        RED8(sa0);
        RED8(sa1);
        LD4x2(a2, aa + (size_t)DIM + hbase + j0);
    }

    float yv0 = 0.f, yv1 = 0.f;
    float* const ybase = y + hbase + r0;

// Step body. SLOT = t&7 (operands), SLOT2 = (t+2)&7 (a_{t+2} prefetch).
// a2 holds a_{t+1}; sa0/sa1 hold sa_t.
#define STEPBODY(T, SLOT, SLOT2) do { \
    const float* sl  = &ring[warp][SLOT][0]; \
    const float* sl2 = &ring[warp][SLOT2][0]; \
    u64 w2[4], k2[4], b2[4], r2[4]; \
    LD4x2(w2, sl + j0); \
    LD4x2(k2, sl + 64 + j0); \
    LD4x2(b2, sl + 192 + j0); \
    LD4x2(r2, sl + 256 + j0); \
    const float2 vpair = *(const float2*)(sl + 320 + g * 2); \
    /* deferred y_{t-1} reduction (independent) */ \
    { \
        float u0 = yv0, u1 = yv1; \
        RED8(u0); \
        RED8(u1); \
        int tprev = (T) - ((T) != 0); \
        if (lane8 == 0) *(float2*)&ybase[(size_t)tprev * DIM] = make_float2(u0, u1); \
    } \
    /* sw = S_t .* w_t (feeds A-dots and update) */ \
    u64 sw0[4], sw1[4]; \
    MUL2(sw0[0], sA[0], w2[0]); MUL2(sw0[1], sA[1], w2[1]); \
    MUL2(sw0[2], sA[2], w2[2]); MUL2(sw0[3], sA[3], w2[3]); \
    MUL2(sw1[0], sB[0], w2[0]); MUL2(sw1[1], sB[1], w2[1]); \
    MUL2(sw1[2], sB[2], w2[2]); MUL2(sw1[3], sB[3], w2[3]); \
    /* lookahead dots vs a_{t+1} (in a2) */ \
    float A0, A1, Bd, Cd; \
    DOT8(A0, sw0, a2); \
    DOT8(A1, sw1, a2); \
    DOT8(Bd, b2, a2); \
    DOT8(Cd, k2, a2); \
    RED8(A0); \
    RED8(A1); \
    RED8(Bd); \
    RED8(Cd); \
    /* state update with KNOWN sa_t (chain-free) */ \
    u64 v0b, v1b, sa0b, sa1b; \
    PACK2(v0b, vpair.x, vpair.x); PACK2(v1b, vpair.y, vpair.y); \
    PACK2(sa0b, sa0, sa0);        PACK2(sa1b, sa1, sa1); \
    _Pragma("unroll") \
    for (int i = 0; i < 4; i++) { \
        u64 t0; FMA2(t0, v0b, k2[i], sw0[i]); \
        FMA2(sA[i], sa0b, b2[i], t0); \
        u64 t1; FMA2(t1, v1b, k2[i], sw1[i]); \
        FMA2(sB[i], sa1b, b2[i], t1); \
    } \
    /* y partial (reduced next iteration) */ \
    u64 yp0, yp1; \
    MUL2(yp0, sA[0], r2[0]); FMA2(yp0, sA[1], r2[1], yp0); \
    FMA2(yp0, sA[2], r2[2], yp0); FMA2(yp0, sA[3], r2[3], yp0); \
    MUL2(yp1, sB[0], r2[0]); FMA2(yp1, sB[1], r2[1], yp1); \
    FMA2(yp1, sB[2], r2[2], yp1); FMA2(yp1, sB[3], r2[3], yp1); \
    { \
        float l0, h0, l1, h1; \
        UNPACK2(l0, h0, yp0); UNPACK2(l1, h1, yp1); \
        yv0 = l0 + h0; yv1 = l1 + h1; \
    } \
    /* sa_{t+1} = A + sa_t*B + v_t*C */ \
    sa0 = fmaf(sa0, Bd, fmaf(vpair.x, Cd, A0)); \
    sa1 = fmaf(sa1, Bd, fmaf(vpair.y, Cd, A1)); \
    /* prefetch a_{t+2} */ \
    LD4x2(a2, sl2 + 128 + j0); \
} while(0)

    // Main loop: constant ring slots, wait_group 5 => slots valid thru t+2.
    for (int tb = 0; tb < TLEN - DEPTH; tb += DEPTH) {
        #pragma unroll
        for (int u = 0; u < DEPTH; u++) {
            const int t = tb + u;
            asm volatile("cp.async.wait_group 5;");
            __syncwarp();
            STEPBODY(t, u, (u + 2) & (DEPTH - 1));
            ISSUE(t + DEPTH, u);
        }
    }

    // Tail: everything staged; stale a2 reads near the end are unused.
    asm volatile("cp.async.wait_group 0;");
    __syncwarp();
    #pragma unroll
    for (int u = 0; u < DEPTH; u++) {
        const int t = TLEN - DEPTH + u;
        STEPBODY(t, u, (u + 2) & (DEPTH - 1));
    }

    // Epilogue: y_{TLEN-1}
    {
        RED8(yv0);
        RED8(yv1);
        if (lane8 == 0) *(float2*)&ybase[(size_t)(TLEN-1) * DIM] = make_float2(yv0, yv1);
    }

    // Final state
    {
        float* sp = sout + ((size_t)h * HS + r0) * HS + j0;
        ulonglong2* p0 = (ulonglong2*)sp;
        ulonglong2* p1 = (ulonglong2*)(sp + HS);
        ulonglong2 x;
        x.x = sA[0]; x.y = sA[1]; p0[0] = x;
        x.x = sA[2]; x.y = sA[3]; p0[1] = x;
        x.x = sB[0]; x.y = sB[1]; p1[0] = x;
        x.x = sB[2]; x.y = sB[3]; p1[1] = x;
    }
}

extern "C" void kernel_launch(void* const* d_in, const int* in_sizes, int n_in,
                              void* d_out, int out_size) {
    int o = (n_in >= 8) ? 1 : 0;
    const float* r  = (const float*)d_in[o + 0];
    const float* w  = (const float*)d_in[o + 1];
    const float* k  = (const float*)d_in[o + 2];
    const float* v  = (const float*)d_in[o + 3];
    const float* a  = (const float*)d_in[o + 4];
    const float* b  = (const float*)d_in[o + 5];
    const float* s0 = (const float*)d_in[o + 6];

    float* y    = (float*)d_out;                  // x: [T, H, 1, N]
    float* sout = y + (size_t)TLEN * DIM;         // state2_out: [H, N, N]

    wkv7_kernel<<<128, 64>>>(r, w, k, v, a, b, s0, y, sout);
}